// round 9
// baseline (speedup 1.0000x reference)
#include <cuda_runtime.h>
#include <math.h>

// SimpleGaussianSplatting: B=4096 rays, N=100000 pts, top-K=10 nearest, weighted blend.
// R4..R9: shared per-ray threshold across a ray-group's 18 slice-warps (atomicMin on
//     monotone-mapped float bits; stale reads are looser => always exact).
//     This collapses the top-10 insertion-body trigger rate (~22% -> ~2%) and lets
//     us double occupancy (18 slices, 288 blocks, 2 blocks/SM, 16 warps/SM).

#define N_PTS    100000
#define SLICES   18
#define L_PTS    5568                  // points per warp-slice (174 chunks of 32)
#define N_PAD    (SLICES * L_PTS)      // 100224
#define N_RAYS   4096
#define K_TOP    10
#define N_GROUPS (N_RAYS / 32)         // 128
#define N_TASKS  (N_GROUPS * SLICES)   // 2304
#define N_BLK    (N_TASKS / 8)         // 288 blocks x 8 warps

#define F_INF __int_as_float(0x7f800000)
#define FULLM 0xffffffffu

// Packed pair layout: g_pk[i] = (x0,x1,y0,y1), g_pk2[i] = (z0,z1,|p0|^2,|p1|^2)
__device__ float4   g_pk [N_PAD / 2];
__device__ float4   g_pk2[N_PAD / 2];
__device__ float4   g_rays[N_RAYS];    // (-2cx, -2cy, -2cz, |c|^2)
__device__ float    g_ps[N_TASKS * K_TOP * 32];
__device__ int      g_pi[N_TASKS * K_TOP * 32];
__device__ int      g_cnt[N_GROUPS];   // tasks completed per ray-group
__device__ unsigned g_thru[N_RAYS];    // shared per-ray threshold, mapped bits

#define FMA2(d, a, b, c) \
    asm("fma.rn.f32x2 %0, %1, %2, %3;" : "=l"(d) : "l"(a), "l"(b), "l"(c))
#define PACK2(d, f) \
    asm("mov.b64 %0, {%1, %1};" : "=l"(d) : "r"(__float_as_int(f)))
#define UNPK2(lo, hi, d) \
    asm("mov.b64 {%0, %1}, %2;" : "=f"(lo), "=f"(hi) : "l"(d))

// Monotone float<->uint mapping: unsigned compare == float compare (all finite floats).
__device__ __forceinline__ unsigned fmap(float f) {
    unsigned b = __float_as_uint(f);
    return (b & 0x80000000u) ? ~b : (b | 0x80000000u);
}
__device__ __forceinline__ float funmap(unsigned u) {
    return __uint_as_float((u & 0x80000000u) ? (u & 0x7fffffffu) : ~u);
}

// Fused prep: point pairs, ray constants, counter + threshold reset. One launch.
__global__ void prep_kernel(const float* __restrict__ xyz,
                            const float* __restrict__ ro,
                            const float* __restrict__ rd) {
    int i = blockIdx.x * blockDim.x + threadIdx.x;
    if (i < N_PAD / 2) {
        int p0 = 2 * i, p1 = 2 * i + 1;
        float x0 = 0.f, y0 = 0.f, z0 = 0.f, w0 = F_INF;
        float x1 = 0.f, y1 = 0.f, z1 = 0.f, w1 = F_INF;
        if (p0 < N_PTS) {
            x0 = xyz[3 * p0 + 0]; y0 = xyz[3 * p0 + 1]; z0 = xyz[3 * p0 + 2];
            w0 = x0 * x0 + y0 * y0 + z0 * z0;
        }
        if (p1 < N_PTS) {
            x1 = xyz[3 * p1 + 0]; y1 = xyz[3 * p1 + 1]; z1 = xyz[3 * p1 + 2];
            w1 = x1 * x1 + y1 * y1 + z1 * z1;
        }
        g_pk [i] = make_float4(x0, x1, y0, y1);
        g_pk2[i] = make_float4(z0, z1, w0, w1);
    }
    if (i < N_RAYS) {
        float cx = ro[3 * i + 0] + 3.f * rd[3 * i + 0];
        float cy = ro[3 * i + 1] + 3.f * rd[3 * i + 1];
        float cz = ro[3 * i + 2] + 3.f * rd[3 * i + 2];
        g_rays[i] = make_float4(-2.f * cx, -2.f * cy, -2.f * cz,
                                cx * cx + cy * cy + cz * cz);
        g_thru[i] = 0xffffffffu;       // unmaps to NaN; fminf(x,NaN)=x => +inf start
    }
    if (i < N_GROUPS) g_cnt[i] = 0;    // deterministic reset per replay
}

__device__ __forceinline__ float sigmoidf_(float x) {
    return 1.f / (1.f + expf(-x));
}

// Branchless sorted insert (ascending); s=+inf is a no-op.
__device__ __forceinline__ void topk_insert(float (&sa)[K_TOP], int (&ia)[K_TOP],
                                            float s, int vi) {
    bool cc[K_TOP];
#pragma unroll
    for (int j = 0; j < K_TOP; ++j) cc[j] = s < sa[j];
#pragma unroll
    for (int j = K_TOP - 1; j >= 1; --j) {
        sa[j] = cc[j - 1] ? sa[j - 1] : (cc[j] ? s  : sa[j]);
        ia[j] = cc[j - 1] ? ia[j - 1] : (cc[j] ? vi : ia[j]);
    }
    sa[0] = cc[0] ? s  : sa[0];
    ia[0] = cc[0] ? vi : ia[0];
}

__global__ __launch_bounds__(256, 2)
void scan_kernel(const float* __restrict__ fdc,
                 const float* __restrict__ opac,
                 float* __restrict__ out) {
    __shared__ ulonglong2 sA[8][32];   // (x0x1, y0y1) bit-packed
    __shared__ ulonglong2 sB[8][32];   // (z0z1, w0w1)

    const int lane = threadIdx.x & 31;
    const int w    = threadIdx.x >> 5;
    const int task  = blockIdx.x * 8 + w;         // 0..2303
    const int group = task / SLICES;              // 0..127
    const int slice = task - group * SLICES;      // 0..17
    const int ray   = group * 32 + lane;

    const float4 rc = g_rays[ray];
    unsigned long long rcx2, rcy2, rcz2;
    PACK2(rcx2, rc.x);
    PACK2(rcy2, rc.y);
    PACK2(rcz2, rc.z);

    float sa[K_TOP];
    int   ia[K_TOP];
#pragma unroll
    for (int j = 0; j < K_TOP; ++j) { sa[j] = F_INF; ia[j] = 0; }

    const ulonglong2* __restrict__ gA = reinterpret_cast<const ulonglong2*>(g_pk);
    const ulonglong2* __restrict__ gB = reinterpret_cast<const ulonglong2*>(g_pk2);
    const int pbase = slice * (L_PTS / 2);        // pair index base (2784/slice)

    ulonglong2 nA = gA[pbase + lane];             // prefetch chunk 0
    ulonglong2 nB = gB[pbase + lane];
    unsigned   tgu = __ldcg(&g_thru[ray]);        // prefetch shared threshold

    float lastpub = F_INF;                        // last value we published

    for (int c = 0; c < L_PTS / 2; c += 32) {
        __syncwarp();
        sA[w][lane] = nA;
        sB[w][lane] = nB;
        __syncwarp();
        const float thrG = funmap(tgu);           // stale => looser => still exact
        if (c + 32 < L_PTS / 2) {
            nA = gA[pbase + c + 32 + lane];       // hide L2 latency
            nB = gB[pbase + c + 32 + lane];
            tgu = __ldcg(&g_thru[ray]);
        }
        float thr_eff = fminf(sa[K_TOP - 1], thrG);

#pragma unroll 4
        for (int k = 0; k < 32; ++k) {
            ulonglong2 A = sA[w][k];              // broadcast LDS.128
            ulonglong2 B = sB[w][k];
            unsigned long long t;
            FMA2(t, rcz2, B.x, B.y);              // z*rcz + |p|^2   (2 pts)
            FMA2(t, rcy2, A.y, t);                // + y*rcy
            FMA2(t, rcx2, A.x, t);                // + x*rcx
            float s0, s1;
            UNPK2(s0, s1, t);
            const bool c0 = s0 < thr_eff;
            const bool c1 = s1 < thr_eff;
            if (__any_sync(FULLM, c0 || c1)) {    // rare (~2%) with shared threshold
                const int pi = (pbase + c + k) * 2;
                const float e0 = c0 ? s0 : F_INF;
                const float e1 = c1 ? s1 : F_INF;
                if (__any_sync(FULLM, c0)) topk_insert(sa, ia, e0, pi);
                if (__any_sync(FULLM, c1)) topk_insert(sa, ia, e1, pi + 1);
                const float s9 = sa[K_TOP - 1];
                if (s9 < lastpub) {               // publish improved 10th-best
                    lastpub = s9;
                    atomicMin(&g_thru[ray], fmap(s9));
                }
                thr_eff = fminf(s9, thrG);
            }
        }
    }

    // publish sorted per-task candidates, coalesced by lane
#pragma unroll
    for (int j = 0; j < K_TOP; ++j) {
        g_ps[(task * K_TOP + j) * 32 + lane] = sa[j];
        g_pi[(task * K_TOP + j) * 32 + lane] = ia[j];
    }

    // ---- in-kernel merge: last task of this ray-group merges + shades ----
    __threadfence();                              // release g_ps/g_pi
    int done = 0;
    if (lane == 0) done = atomicAdd(&g_cnt[group], 1);
    done = __shfl_sync(FULLM, done, 0);
    if (done != SLICES - 1) return;               // not last -> exit
    __threadfence();                              // acquire other tasks' writes

    float ms[K_TOP];
    int   mi[K_TOP];
#pragma unroll
    for (int j = 0; j < K_TOP; ++j) { ms[j] = F_INF; mi[j] = 0; }

    for (int s = 0; s < SLICES; ++s) {
        const int t0 = (group * SLICES + s) * K_TOP;
        for (int k = 0; k < K_TOP; ++k) {
            float v = __ldcg(&g_ps[(t0 + k) * 32 + lane]);
            if (v >= ms[K_TOP - 1]) break;        // source sorted -> rest can't win
            topk_insert(ms, mi, v, __ldcg(&g_pi[(t0 + k) * 32 + lane]));
        }
    }

    // shade: d = sqrt(|c|^2 + s), wt = exp(-0.1 d) * sigmoid(op), normalized blend
    const float h = rc.w;
    float wsum = 0.f, a0 = 0.f, a1 = 0.f, a2 = 0.f;
#pragma unroll
    for (int k = 0; k < K_TOP; ++k) {
        int id   = mi[k];
        float d  = sqrtf(fmaxf(h + ms[k], 0.f));
        float wt = expf(-0.1f * d) * sigmoidf_(opac[id]);
        a0 += wt * sigmoidf_(fdc[3 * id + 0]);
        a1 += wt * sigmoidf_(fdc[3 * id + 1]);
        a2 += wt * sigmoidf_(fdc[3 * id + 2]);
        wsum += wt;
    }
    float inv = 1.f / (wsum + 1e-8f);
    out[3 * ray + 0] = a0 * inv;
    out[3 * ray + 1] = a1 * inv;
    out[3 * ray + 2] = a2 * inv;
}

extern "C" void kernel_launch(void* const* d_in, const int* in_sizes, int n_in,
                              void* d_out, int out_size) {
    const float* ro  = (const float*)d_in[0];   // rays_o      [4096,3]
    const float* rd  = (const float*)d_in[1];   // rays_d      [4096,3]
    const float* xyz = (const float*)d_in[2];   // xyz         [100000,3]
    const float* fdc = (const float*)d_in[3];   // features_dc [100000,1,3]
    const float* op  = (const float*)d_in[4];   // opacity     [100000,1]
    float* out = (float*)d_out;                 // [4096,3] fp32

    prep_kernel<<<(N_PAD / 2 + 255) / 256, 256>>>(xyz, ro, rd);
    scan_kernel<<<N_BLK, 256>>>(fdc, op, out);
}

// round 15
// speedup vs baseline: 1.1824x; 1.1824x over previous
#include <cuda_runtime.h>
#include <math.h>

// SimpleGaussianSplatting: B=4096 rays, N=100000 pts, top-K=10 nearest, weighted blend.
// R10..R15: batched guard. R9 showed alu 30% == per-POINT guard overhead (setp/vote/bra),
//      not the insert body. Now: 8 points per guard batch -> 4 independent FMA2
//      chains, 7-FMNMX min tree, ONE setp+vote+branch per 8 points. Rare path uses
//      8 per-point votes -> warp-uniform bitmask -> uniform-branch inserts.
//      Shared per-ray threshold (atomicMin, monotone-mapped bits) keeps the
//      per-point trigger ~3% regardless of slicing.

#define N_PTS    100000
#define SLICES   18
#define L_PTS    5568                  // points per warp-slice (174 chunks of 32)
#define N_PAD    (SLICES * L_PTS)      // 100224
#define N_RAYS   4096
#define K_TOP    10
#define N_GROUPS (N_RAYS / 32)         // 128
#define N_TASKS  (N_GROUPS * SLICES)   // 2304
#define N_BLK    (N_TASKS / 8)         // 288 blocks x 8 warps

#define F_INF __int_as_float(0x7f800000)
#define FULLM 0xffffffffu

// Packed pair layout: g_pk[i] = (x0,x1,y0,y1), g_pk2[i] = (z0,z1,|p0|^2,|p1|^2)
__device__ float4   g_pk [N_PAD / 2];
__device__ float4   g_pk2[N_PAD / 2];
__device__ float4   g_rays[N_RAYS];    // (-2cx, -2cy, -2cz, |c|^2)
__device__ float    g_ps[N_TASKS * K_TOP * 32];
__device__ int      g_pi[N_TASKS * K_TOP * 32];
__device__ int      g_cnt[N_GROUPS];   // tasks completed per ray-group
__device__ unsigned g_thru[N_RAYS];    // shared per-ray threshold, mapped bits

#define FMA2(d, a, b, c) \
    asm("fma.rn.f32x2 %0, %1, %2, %3;" : "=l"(d) : "l"(a), "l"(b), "l"(c))
#define PACK2(d, f) \
    asm("mov.b64 %0, {%1, %1};" : "=l"(d) : "r"(__float_as_int(f)))
#define UNPK2(lo, hi, d) \
    asm("mov.b64 {%0, %1}, %2;" : "=f"(lo), "=f"(hi) : "l"(d))

// Monotone float<->uint mapping: unsigned compare == float compare (finite floats).
__device__ __forceinline__ unsigned fmap(float f) {
    unsigned b = __float_as_uint(f);
    return (b & 0x80000000u) ? ~b : (b | 0x80000000u);
}
__device__ __forceinline__ float funmap(unsigned u) {
    return __uint_as_float((u & 0x80000000u) ? (u & 0x7fffffffu) : ~u);
}

// Fused prep: point pairs, ray constants, counter + threshold reset. One launch.
__global__ void prep_kernel(const float* __restrict__ xyz,
                            const float* __restrict__ ro,
                            const float* __restrict__ rd) {
    int i = blockIdx.x * blockDim.x + threadIdx.x;
    if (i < N_PAD / 2) {
        int p0 = 2 * i, p1 = 2 * i + 1;
        float x0 = 0.f, y0 = 0.f, z0 = 0.f, w0 = F_INF;
        float x1 = 0.f, y1 = 0.f, z1 = 0.f, w1 = F_INF;
        if (p0 < N_PTS) {
            x0 = xyz[3 * p0 + 0]; y0 = xyz[3 * p0 + 1]; z0 = xyz[3 * p0 + 2];
            w0 = x0 * x0 + y0 * y0 + z0 * z0;
        }
        if (p1 < N_PTS) {
            x1 = xyz[3 * p1 + 0]; y1 = xyz[3 * p1 + 1]; z1 = xyz[3 * p1 + 2];
            w1 = x1 * x1 + y1 * y1 + z1 * z1;
        }
        g_pk [i] = make_float4(x0, x1, y0, y1);
        g_pk2[i] = make_float4(z0, z1, w0, w1);
    }
    if (i < N_RAYS) {
        float cx = ro[3 * i + 0] + 3.f * rd[3 * i + 0];
        float cy = ro[3 * i + 1] + 3.f * rd[3 * i + 1];
        float cz = ro[3 * i + 2] + 3.f * rd[3 * i + 2];
        g_rays[i] = make_float4(-2.f * cx, -2.f * cy, -2.f * cz,
                                cx * cx + cy * cy + cz * cz);
        g_thru[i] = 0xffffffffu;       // unmaps to NaN; fminf(x,NaN)=x => +inf start
    }
    if (i < N_GROUPS) g_cnt[i] = 0;    // deterministic reset per replay
}

__device__ __forceinline__ float sigmoidf_(float x) {
    return 1.f / (1.f + expf(-x));
}

// Branchless sorted insert (ascending); s >= sa[K-1] is a no-op.
__device__ __forceinline__ void topk_insert(float (&sa)[K_TOP], int (&ia)[K_TOP],
                                            float s, int vi) {
    bool cc[K_TOP];
#pragma unroll
    for (int j = 0; j < K_TOP; ++j) cc[j] = s < sa[j];
#pragma unroll
    for (int j = K_TOP - 1; j >= 1; --j) {
        sa[j] = cc[j - 1] ? sa[j - 1] : (cc[j] ? s  : sa[j]);
        ia[j] = cc[j - 1] ? ia[j - 1] : (cc[j] ? vi : ia[j]);
    }
    sa[0] = cc[0] ? s  : sa[0];
    ia[0] = cc[0] ? vi : ia[0];
}

__global__ __launch_bounds__(256, 2)
void scan_kernel(const float* __restrict__ fdc,
                 const float* __restrict__ opac,
                 float* __restrict__ out) {
    __shared__ ulonglong2 sA[8][32];   // (x0x1, y0y1) bit-packed
    __shared__ ulonglong2 sB[8][32];   // (z0z1, w0w1)

    const int lane = threadIdx.x & 31;
    const int w    = threadIdx.x >> 5;
    const int task  = blockIdx.x * 8 + w;         // 0..2303
    const int group = task / SLICES;              // 0..127
    const int slice = task - group * SLICES;      // 0..17
    const int ray   = group * 32 + lane;

    const float4 rc = g_rays[ray];
    unsigned long long rcx2, rcy2, rcz2;
    PACK2(rcx2, rc.x);
    PACK2(rcy2, rc.y);
    PACK2(rcz2, rc.z);

    float sa[K_TOP];
    int   ia[K_TOP];
#pragma unroll
    for (int j = 0; j < K_TOP; ++j) { sa[j] = F_INF; ia[j] = 0; }

    const ulonglong2* __restrict__ gA = reinterpret_cast<const ulonglong2*>(g_pk);
    const ulonglong2* __restrict__ gB = reinterpret_cast<const ulonglong2*>(g_pk2);
    const int pbase = slice * (L_PTS / 2);        // pair index base (2784/slice)

    ulonglong2 nA = gA[pbase + lane];             // prefetch chunk 0
    ulonglong2 nB = gB[pbase + lane];
    unsigned   tgu = __ldcg(&g_thru[ray]);        // prefetch shared threshold

    float lastpub = F_INF;                        // last value we published

    for (int c = 0; c < L_PTS / 2; c += 32) {
        __syncwarp();
        sA[w][lane] = nA;
        sB[w][lane] = nB;
        __syncwarp();
        const float thrG = funmap(tgu);           // stale => looser => still exact
        if (c + 32 < L_PTS / 2) {
            nA = gA[pbase + c + 32 + lane];       // hide L2 latency
            nB = gB[pbase + c + 32 + lane];
            tgu = __ldcg(&g_thru[ray]);
        }
        float thr_eff = fminf(sa[K_TOP - 1], thrG);

        // 8 batches of 4 pairs (8 points): one setp+vote+branch per batch.
#pragma unroll 4
        for (int k = 0; k < 32; k += 4) {
            ulonglong2 A0 = sA[w][k + 0], B0 = sB[w][k + 0];
            ulonglong2 A1 = sA[w][k + 1], B1 = sB[w][k + 1];
            ulonglong2 A2 = sA[w][k + 2], B2 = sB[w][k + 2];
            ulonglong2 A3 = sA[w][k + 3], B3 = sB[w][k + 3];
            unsigned long long t0, t1, t2, t3;
            FMA2(t0, rcz2, B0.x, B0.y);           // 4 independent chains -> ILP
            FMA2(t1, rcz2, B1.x, B1.y);
            FMA2(t2, rcz2, B2.x, B2.y);
            FMA2(t3, rcz2, B3.x, B3.y);
            FMA2(t0, rcy2, A0.y, t0);
            FMA2(t1, rcy2, A1.y, t1);
            FMA2(t2, rcy2, A2.y, t2);
            FMA2(t3, rcy2, A3.y, t3);
            FMA2(t0, rcx2, A0.x, t0);
            FMA2(t1, rcx2, A1.x, t1);
            FMA2(t2, rcx2, A2.x, t2);
            FMA2(t3, rcx2, A3.x, t3);
            float s0, s1, s2, s3, s4, s5, s6, s7;
            UNPK2(s0, s1, t0);
            UNPK2(s2, s3, t1);
            UNPK2(s4, s5, t2);
            UNPK2(s6, s7, t3);
            // min tree: 7 FMNMX, depth 3
            float mn = fminf(fminf(fminf(s0, s1), fminf(s2, s3)),
                             fminf(fminf(s4, s5), fminf(s6, s7)));
            if (__any_sync(FULLM, mn < thr_eff)) {            // ~24% of batches
                const int pib = (pbase + c + k) * 2;
                unsigned bits = 0;
                if (__any_sync(FULLM, s0 < thr_eff)) bits |= 0x01u;
                if (__any_sync(FULLM, s1 < thr_eff)) bits |= 0x02u;
                if (__any_sync(FULLM, s2 < thr_eff)) bits |= 0x04u;
                if (__any_sync(FULLM, s3 < thr_eff)) bits |= 0x08u;
                if (__any_sync(FULLM, s4 < thr_eff)) bits |= 0x10u;
                if (__any_sync(FULLM, s5 < thr_eff)) bits |= 0x20u;
                if (__any_sync(FULLM, s6 < thr_eff)) bits |= 0x40u;
                if (__any_sync(FULLM, s7 < thr_eff)) bits |= 0x80u;
                // warp-uniform tests; non-passing lanes insert +inf (no-op)
                if (bits & 0x01u) topk_insert(sa, ia, (s0 < thr_eff) ? s0 : F_INF, pib + 0);
                if (bits & 0x02u) topk_insert(sa, ia, (s1 < thr_eff) ? s1 : F_INF, pib + 1);
                if (bits & 0x04u) topk_insert(sa, ia, (s2 < thr_eff) ? s2 : F_INF, pib + 2);
                if (bits & 0x08u) topk_insert(sa, ia, (s3 < thr_eff) ? s3 : F_INF, pib + 3);
                if (bits & 0x10u) topk_insert(sa, ia, (s4 < thr_eff) ? s4 : F_INF, pib + 4);
                if (bits & 0x20u) topk_insert(sa, ia, (s5 < thr_eff) ? s5 : F_INF, pib + 5);
                if (bits & 0x40u) topk_insert(sa, ia, (s6 < thr_eff) ? s6 : F_INF, pib + 6);
                if (bits & 0x80u) topk_insert(sa, ia, (s7 < thr_eff) ? s7 : F_INF, pib + 7);
                const float s9 = sa[K_TOP - 1];
                if (s9 < lastpub) {               // publish improved 10th-best
                    lastpub = s9;
                    atomicMin(&g_thru[ray], fmap(s9));
                }
                thr_eff = fminf(s9, thrG);
            }
        }
    }

    // publish sorted per-task candidates, coalesced by lane
#pragma unroll
    for (int j = 0; j < K_TOP; ++j) {
        g_ps[(task * K_TOP + j) * 32 + lane] = sa[j];
        g_pi[(task * K_TOP + j) * 32 + lane] = ia[j];
    }

    // ---- in-kernel merge: last task of this ray-group merges + shades ----
    __threadfence();                              // release g_ps/g_pi
    int done = 0;
    if (lane == 0) done = atomicAdd(&g_cnt[group], 1);
    done = __shfl_sync(FULLM, done, 0);
    if (done != SLICES - 1) return;               // not last -> exit
    __threadfence();                              // acquire other tasks' writes

    float ms[K_TOP];
    int   mi[K_TOP];
#pragma unroll
    for (int j = 0; j < K_TOP; ++j) { ms[j] = F_INF; mi[j] = 0; }

    for (int s = 0; s < SLICES; ++s) {
        const int t0 = (group * SLICES + s) * K_TOP;
        for (int k = 0; k < K_TOP; ++k) {
            float v = __ldcg(&g_ps[(t0 + k) * 32 + lane]);
            if (v >= ms[K_TOP - 1]) break;        // source sorted -> rest can't win
            topk_insert(ms, mi, v, __ldcg(&g_pi[(t0 + k) * 32 + lane]));
        }
    }

    // shade: d = sqrt(|c|^2 + s), wt = exp(-0.1 d) * sigmoid(op), normalized blend
    const float h = rc.w;
    float wsum = 0.f, a0 = 0.f, a1 = 0.f, a2 = 0.f;
#pragma unroll
    for (int k = 0; k < K_TOP; ++k) {
        int id   = mi[k];
        float d  = sqrtf(fmaxf(h + ms[k], 0.f));
        float wt = expf(-0.1f * d) * sigmoidf_(opac[id]);
        a0 += wt * sigmoidf_(fdc[3 * id + 0]);
        a1 += wt * sigmoidf_(fdc[3 * id + 1]);
        a2 += wt * sigmoidf_(fdc[3 * id + 2]);
        wsum += wt;
    }
    float inv = 1.f / (wsum + 1e-8f);
    out[3 * ray + 0] = a0 * inv;
    out[3 * ray + 1] = a1 * inv;
    out[3 * ray + 2] = a2 * inv;
}

extern "C" void kernel_launch(void* const* d_in, const int* in_sizes, int n_in,
                              void* d_out, int out_size) {
    const float* ro  = (const float*)d_in[0];   // rays_o      [4096,3]
    const float* rd  = (const float*)d_in[1];   // rays_d      [4096,3]
    const float* xyz = (const float*)d_in[2];   // xyz         [100000,3]
    const float* fdc = (const float*)d_in[3];   // features_dc [100000,1,3]
    const float* op  = (const float*)d_in[4];   // opacity     [100000,1]
    float* out = (float*)d_out;                 // [4096,3] fp32

    prep_kernel<<<(N_PAD / 2 + 255) / 256, 256>>>(xyz, ro, rd);
    scan_kernel<<<N_BLK, 256>>>(fdc, op, out);
}